// round 9
// baseline (speedup 1.0000x reference)
#include <cuda_runtime.h>
#include <cstdint>

// Shapes (fixed): B=4, N=1024, C=64
#define B_ 4
#define N_ 1024
#define C_ 64
#define M_ (B_ * N_)
#define TI 8                  // i-rows per att block (4 packed pairs)

typedef unsigned long long u64;

// Prepared projections: channel c with (c&7)>=5 stores tanh(proj), else raw.
__device__ float g_x1[M_ * C_];
__device__ float g_x2[M_ * C_];
__device__ float g_psum[M_ * 2];   // per-row partial softmax sums (2 j-halves)

__device__ __forceinline__ float tanh_fast(float x) {
    float y; asm("tanh.approx.f32 %0, %1;" : "=f"(y) : "f"(x)); return y;
}
__device__ __forceinline__ u64 pk(float lo, float hi) {
    u64 r; asm("mov.b64 %0, {%1, %2};" : "=l"(r) : "f"(lo), "f"(hi)); return r;
}
__device__ __forceinline__ float2 upk(u64 v) {
    float2 f; asm("mov.b64 {%0, %1}, %2;" : "=f"(f.x), "=f"(f.y) : "l"(v)); return f;
}
__device__ __forceinline__ u64 add2(u64 a, u64 b) {
    u64 r; asm("add.rn.f32x2 %0, %1, %2;" : "=l"(r) : "l"(a), "l"(b)); return r;
}
__device__ __forceinline__ u64 mul2(u64 a, u64 b) {
    u64 r; asm("mul.rn.f32x2 %0, %1, %2;" : "=l"(r) : "l"(a), "l"(b)); return r;
}
__device__ __forceinline__ u64 fma2(u64 a, u64 b, u64 c) {
    u64 r; asm("fma.rn.f32x2 %0, %1, %2, %3;" : "=l"(r) : "l"(a), "l"(b), "l"(c)); return r;
}
__device__ __forceinline__ u64 tanh2_mufu(u64 x) {
    u64 r;
    asm("{\n\t.reg .f32 a,b;\n\t"
        "mov.b64 {a,b}, %1;\n\t"
        "tanh.approx.f32 a, a;\n\t"
        "tanh.approx.f32 b, b;\n\t"
        "mov.b64 %0, {a,b};\n\t}" : "=l"(r) : "l"(x));
    return r;
}
__device__ __forceinline__ u64 rcp2_seed64(u64 d) {
    return 0x7EF311C37EF311C3ULL - d;
}
__device__ __forceinline__ u64 neg2(u64 x) { return x ^ 0x8000000080000000ULL; }

// ---------------------------------------------------------------------------
// Kernel 1: projections. Grid 1024 x 256 thr; thread owns one (row, d) for
// BOTH W1 and W2. W rows via float4 global loads (16KB set, L1-resident);
// x row broadcast from shared. Channels (d&7)>=5 store tanh(proj).
// ---------------------------------------------------------------------------
__global__ __launch_bounds__(256) void proj_kernel(
    const float* __restrict__ x,
    const float* __restrict__ W1,
    const float* __restrict__ W2)
{
    __shared__ float xs[4 * C_];

    const int tid  = threadIdx.x;
    const int row0 = blockIdx.x * 4;
    const int r    = tid >> 6;         // 0..3
    const int d    = tid & 63;

    xs[tid] = x[row0 * C_ + tid];
    __syncthreads();

    const float4* w1r = reinterpret_cast<const float4*>(W1 + d * C_);
    const float4* w2r = reinterpret_cast<const float4*>(W2 + d * C_);
    const float*  xr  = xs + r * C_;

    float a1 = 0.f, a2 = 0.f;
    #pragma unroll 4
    for (int c4 = 0; c4 < C_ / 4; ++c4) {
        const float4 w1 = w1r[c4];
        const float4 w2 = w2r[c4];
        const float x0 = xr[c4 * 4 + 0];
        const float x1 = xr[c4 * 4 + 1];
        const float x2v = xr[c4 * 4 + 2];
        const float x3 = xr[c4 * 4 + 3];
        a1 = fmaf(x0, w1.x, a1); a1 = fmaf(x1, w1.y, a1);
        a1 = fmaf(x2v, w1.z, a1); a1 = fmaf(x3, w1.w, a1);
        a2 = fmaf(x0, w2.x, a2); a2 = fmaf(x1, w2.y, a2);
        a2 = fmaf(x2v, w2.z, a2); a2 = fmaf(x3, w2.w, a2);
    }

    const bool idp = (d & 7) >= 5;
    g_x1[(row0 + r) * C_ + d] = idp ? tanh_fast(a1) : a1;
    g_x2[(row0 + r) * C_ + d] = idp ? tanh_fast(a2) : a2;
}

// ---------------------------------------------------------------------------
// Kernel 2: att mainloop. Grid (128, 2, 4) = 1024 blocks x 256 thr, 5/SM.
// Block owns TI=8 i-rows and HALF the j range (512 j's, 2 chunks of 256).
// Per 8-channel group: 5 via MUFU tanh(a+b), 3 via addition theorem
// (t1+t2)/(1+t1*t2) on the FMA pipe (2-Newton recip) — pipes balanced.
// exp(att) written straight to out; per-row partial sums -> g_psum.
// ---------------------------------------------------------------------------
__global__ __launch_bounds__(256, 5) void att_kernel(
    const float* __restrict__ w3,
    float* __restrict__ out)
{
    __shared__ u64  x1p_s[C_ * 4];     // [c*4+ip] = (prep1[2ip][c], prep1[2ip+1][c])
    __shared__ u64  w2s[C_];           // (w3[c], w3[c])
    __shared__ float red[8][TI];

    const int tid  = threadIdx.x;
    const int b    = blockIdx.z;
    const int jh   = blockIdx.y;       // j-half
    const int i0   = blockIdx.x * TI;
    const int lane = tid & 31;
    const int warp = tid >> 5;

    {
        int c = tid >> 2, ip = tid & 3;
        const float* base = g_x1 + (size_t)(b * N_ + i0) * C_;
        x1p_s[tid] = pk(base[(2 * ip) * C_ + c], base[(2 * ip + 1) * C_ + c]);
    }
    if (tid < C_) w2s[tid] = pk(w3[tid], w3[tid]);
    __syncthreads();

    const u64 ONE_ = pk(1.0f, 1.0f);
    const u64 TWO_ = pk(2.0f, 2.0f);

    const float* x2b = g_x2 + (size_t)b * N_ * C_;

    float ps[TI];
    #pragma unroll
    for (int i = 0; i < TI; ++i) ps[i] = 0.f;

    for (int chunk = 0; chunk < 2; ++chunk) {
        const int j = jh * 512 + chunk * 256 + tid;
        const float4* xr = reinterpret_cast<const float4*>(x2b + (size_t)j * C_);

        u64 acc2[4] = {0ull, 0ull, 0ull, 0ull};

        for (int g = 0; g < 8; ++g) {            // 8 channels per group
            const float4 v0 = xr[g * 2];
            const float4 v1 = xr[g * 2 + 1];
            const float zs[8] = {v0.x, v0.y, v0.z, v0.w, v1.x, v1.y, v1.z, v1.w};

            #pragma unroll
            for (int k = 0; k < 8; ++k) {
                const int c = g * 8 + k;
                const u64 zz = pk(zs[k], zs[k]);
                const u64 wc = w2s[c];
                if (k < 5) {
                    // MUFU channel (raw values)
                    #pragma unroll
                    for (int ip = 0; ip < 4; ++ip) {
                        u64 s2 = add2(x1p_s[c * 4 + ip], zz);
                        acc2[ip] = fma2(wc, tanh2_mufu(s2), acc2[ip]);
                    }
                } else {
                    // identity channel (pre-tanh'd values), 2-Newton recip
                    #pragma unroll
                    for (int ip = 0; ip < 4; ++ip) {
                        const u64 t1 = x1p_s[c * 4 + ip];
                        u64 num = add2(t1, zz);
                        u64 den = fma2(t1, zz, ONE_);
                        u64 nd  = neg2(den);
                        u64 r   = rcp2_seed64(den);
                        u64 e   = fma2(nd, r, TWO_); r = mul2(r, e);
                        e       = fma2(nd, r, TWO_); r = mul2(r, e);
                        acc2[ip] = fma2(wc, mul2(num, r), acc2[ip]);
                    }
                }
            }
        }
        // exp + direct global store + per-row partial sums (no max pass:
        // |att| <= sum|w3| ~ 6.4, exp well within fp32 range)
        #pragma unroll
        for (int ip = 0; ip < 4; ++ip) {
            float2 a = upk(acc2[ip]);
            float e0 = __expf(a.x);
            float e1 = __expf(a.y);
            out[((size_t)(b * N_ + i0 + 2 * ip))     * N_ + j] = e0;
            out[((size_t)(b * N_ + i0 + 2 * ip + 1)) * N_ + j] = e1;
            ps[2 * ip]     += e0;
            ps[2 * ip + 1] += e1;
        }
    }

    // ---- block reduction of per-row partial sums ----
    #pragma unroll
    for (int i = 0; i < TI; ++i) {
        #pragma unroll
        for (int o = 16; o > 0; o >>= 1)
            ps[i] += __shfl_xor_sync(0xFFFFFFFFu, ps[i], o);
        if (lane == 0) red[warp][i] = ps[i];
    }
    __syncthreads();
    if (tid < TI) {
        float s = 0.f;
        #pragma unroll
        for (int w = 0; w < 8; ++w) s += red[w][tid];
        g_psum[(size_t)(b * N_ + i0 + tid) * 2 + jh] = s;
    }
}

// ---------------------------------------------------------------------------
// Kernel 3: normalize. 4096 blocks (one row each) x 256 threads (one float4).
// out stays L2-resident between kernels.
// ---------------------------------------------------------------------------
__global__ __launch_bounds__(256) void scale_kernel(float* __restrict__ out)
{
    const int row = blockIdx.x;
    const float s = g_psum[row * 2] + g_psum[row * 2 + 1];
    const float inv = __fdividef(1.f, s);
    float4* o = reinterpret_cast<float4*>(out + (size_t)row * N_);
    float4 v = o[threadIdx.x];
    v.x *= inv; v.y *= inv; v.z *= inv; v.w *= inv;
    o[threadIdx.x] = v;
}

extern "C" void kernel_launch(void* const* d_in, const int* in_sizes, int n_in,
                              void* d_out, int out_size)
{
    const float* x  = (const float*)d_in[0];
    const float* W1 = (const float*)d_in[1];
    const float* W2 = (const float*)d_in[2];
    const float* w3 = (const float*)d_in[3];
    float* out = (float*)d_out;

    proj_kernel<<<M_ / 4, 256>>>(x, W1, W2);

    dim3 grid(N_ / TI, 2, B_);
    att_kernel<<<grid, 256>>>(w3, out);

    scale_kernel<<<M_, 256>>>(out);
}

// round 10
// speedup vs baseline: 1.2985x; 1.2985x over previous
#include <cuda_runtime.h>
#include <cstdint>

// Shapes (fixed): B=4, N=1024, C=64
#define B_ 4
#define N_ 1024
#define C_ 64
#define M_ (B_ * N_)
#define TI 8                  // i-rows per att block (4 packed pairs)

typedef unsigned long long u64;

// Prepared projections: channel c with (c&7)>=5 stores tanh(proj), else raw.
__device__ float g_x1[M_ * C_];
__device__ float g_x2[M_ * C_];
__device__ float g_psum[M_ * 2];   // per-row partial softmax sums (2 j-halves)

__device__ __forceinline__ float tanh_fast(float x) {
    float y; asm("tanh.approx.f32 %0, %1;" : "=f"(y) : "f"(x)); return y;
}
__device__ __forceinline__ u64 pk(float lo, float hi) {
    u64 r; asm("mov.b64 %0, {%1, %2};" : "=l"(r) : "f"(lo), "f"(hi)); return r;
}
__device__ __forceinline__ float2 upk(u64 v) {
    float2 f; asm("mov.b64 {%0, %1}, %2;" : "=f"(f.x), "=f"(f.y) : "l"(v)); return f;
}
__device__ __forceinline__ u64 add2(u64 a, u64 b) {
    u64 r; asm("add.rn.f32x2 %0, %1, %2;" : "=l"(r) : "l"(a), "l"(b)); return r;
}
__device__ __forceinline__ u64 mul2(u64 a, u64 b) {
    u64 r; asm("mul.rn.f32x2 %0, %1, %2;" : "=l"(r) : "l"(a), "l"(b)); return r;
}
__device__ __forceinline__ u64 fma2(u64 a, u64 b, u64 c) {
    u64 r; asm("fma.rn.f32x2 %0, %1, %2, %3;" : "=l"(r) : "l"(a), "l"(b), "l"(c)); return r;
}
__device__ __forceinline__ u64 tanh2_mufu(u64 x) {
    u64 r;
    asm("{\n\t.reg .f32 a,b;\n\t"
        "mov.b64 {a,b}, %1;\n\t"
        "tanh.approx.f32 a, a;\n\t"
        "tanh.approx.f32 b, b;\n\t"
        "mov.b64 %0, {a,b};\n\t}" : "=l"(r) : "l"(x));
    return r;
}
__device__ __forceinline__ u64 rcp2_seed64(u64 d) {
    return 0x7EF311C37EF311C3ULL - d;
}
__device__ __forceinline__ u64 neg2(u64 x) { return x ^ 0x8000000080000000ULL; }

// ---------------------------------------------------------------------------
// Kernel 1: projections. 1024 blocks x 256 thr, 4 rows per block, one (r,d)
// cell per thread. W1/W2 staged to padded smem via coalesced float4 loads;
// LDS in the dot loop is conflict-free (stride 65). Channels (d&7)>=5 store
// tanh(proj) (identity-path preparation).
// ---------------------------------------------------------------------------
__global__ __launch_bounds__(256) void proj_kernel(
    const float* __restrict__ x,
    const float* __restrict__ W1,
    const float* __restrict__ W2)
{
    __shared__ float W1s[C_ * 65];
    __shared__ float W2s[C_ * 65];
    __shared__ float xs[4 * C_];

    const int tid  = threadIdx.x;
    const int row0 = blockIdx.x * 4;
    const int r    = tid >> 6;         // 0..3
    const int d    = tid & 63;

    const float4* W1v = reinterpret_cast<const float4*>(W1);
    const float4* W2v = reinterpret_cast<const float4*>(W2);
    #pragma unroll
    for (int q = 0; q < 4; ++q) {
        int k4 = q * 256 + tid;        // 0..1023 float4 index
        int dd = k4 >> 4;
        int cc = (k4 & 15) * 4;
        float4 w1 = W1v[k4];
        float4 w2 = W2v[k4];
        float* p1 = W1s + dd * 65 + cc;
        float* p2 = W2s + dd * 65 + cc;
        p1[0] = w1.x; p1[1] = w1.y; p1[2] = w1.z; p1[3] = w1.w;
        p2[0] = w2.x; p2[1] = w2.y; p2[2] = w2.z; p2[3] = w2.w;
    }
    xs[tid] = x[row0 * C_ + tid];
    __syncthreads();

    const float* xr = xs + r * C_;
    float a1 = 0.f, a2 = 0.f;
    #pragma unroll 8
    for (int c = 0; c < C_; ++c) {
        const float xv = xr[c];                 // broadcast LDS
        a1 = fmaf(xv, W1s[d * 65 + c], a1);     // conflict-free LDS
        a2 = fmaf(xv, W2s[d * 65 + c], a2);
    }

    const bool idp = (d & 7) >= 5;
    g_x1[(row0 + r) * C_ + d] = idp ? tanh_fast(a1) : a1;
    g_x2[(row0 + r) * C_ + d] = idp ? tanh_fast(a2) : a2;
}

// ---------------------------------------------------------------------------
// Kernel 2: att mainloop. Grid (128, 2, 4) = 1024 blocks x 256 thr, 5/SM.
// Block owns TI=8 i-rows and HALF the j range (512 j's, 2 chunks of 256).
// Per 8-channel group: 5 via MUFU tanh(a+b), 3 via addition theorem
// (t1+t2)/(1+t1*t2) on the FMA pipe (2-Newton recip) — pipes balanced.
// exp(att) written straight to out; per-row partial sums -> g_psum.
// ---------------------------------------------------------------------------
__global__ __launch_bounds__(256, 5) void att_kernel(
    const float* __restrict__ w3,
    float* __restrict__ out)
{
    __shared__ u64  x1p_s[C_ * 4];     // [c*4+ip] = (prep1[2ip][c], prep1[2ip+1][c])
    __shared__ u64  w2s[C_];           // (w3[c], w3[c])
    __shared__ float red[8][TI];

    const int tid  = threadIdx.x;
    const int b    = blockIdx.z;
    const int jh   = blockIdx.y;       // j-half
    const int i0   = blockIdx.x * TI;
    const int lane = tid & 31;
    const int warp = tid >> 5;

    {
        int c = tid >> 2, ip = tid & 3;
        const float* base = g_x1 + (size_t)(b * N_ + i0) * C_;
        x1p_s[tid] = pk(base[(2 * ip) * C_ + c], base[(2 * ip + 1) * C_ + c]);
    }
    if (tid < C_) w2s[tid] = pk(w3[tid], w3[tid]);
    __syncthreads();

    const u64 ONE_ = pk(1.0f, 1.0f);
    const u64 TWO_ = pk(2.0f, 2.0f);

    const float* x2b = g_x2 + (size_t)b * N_ * C_;

    float ps[TI];
    #pragma unroll
    for (int i = 0; i < TI; ++i) ps[i] = 0.f;

    for (int chunk = 0; chunk < 2; ++chunk) {
        const int j = jh * 512 + chunk * 256 + tid;
        const float4* xr = reinterpret_cast<const float4*>(x2b + (size_t)j * C_);

        u64 acc2[4] = {0ull, 0ull, 0ull, 0ull};

        for (int g = 0; g < 8; ++g) {            // 8 channels per group
            const float4 v0 = xr[g * 2];
            const float4 v1 = xr[g * 2 + 1];
            const float zs[8] = {v0.x, v0.y, v0.z, v0.w, v1.x, v1.y, v1.z, v1.w};

            #pragma unroll
            for (int k = 0; k < 8; ++k) {
                const int c = g * 8 + k;
                const u64 zz = pk(zs[k], zs[k]);
                const u64 wc = w2s[c];
                if (k < 5) {
                    // MUFU channel (raw values)
                    #pragma unroll
                    for (int ip = 0; ip < 4; ++ip) {
                        u64 s2 = add2(x1p_s[c * 4 + ip], zz);
                        acc2[ip] = fma2(wc, tanh2_mufu(s2), acc2[ip]);
                    }
                } else {
                    // identity channel (pre-tanh'd values), 2-Newton recip
                    #pragma unroll
                    for (int ip = 0; ip < 4; ++ip) {
                        const u64 t1 = x1p_s[c * 4 + ip];
                        u64 num = add2(t1, zz);
                        u64 den = fma2(t1, zz, ONE_);
                        u64 nd  = neg2(den);
                        u64 r   = rcp2_seed64(den);
                        u64 e   = fma2(nd, r, TWO_); r = mul2(r, e);
                        e       = fma2(nd, r, TWO_); r = mul2(r, e);
                        acc2[ip] = fma2(wc, mul2(num, r), acc2[ip]);
                    }
                }
            }
        }
        // exp + direct global store + per-row partial sums (no max pass:
        // |att| <= sum|w3| ~ 6.4, exp well within fp32 range)
        #pragma unroll
        for (int ip = 0; ip < 4; ++ip) {
            float2 a = upk(acc2[ip]);
            float e0 = __expf(a.x);
            float e1 = __expf(a.y);
            out[((size_t)(b * N_ + i0 + 2 * ip))     * N_ + j] = e0;
            out[((size_t)(b * N_ + i0 + 2 * ip + 1)) * N_ + j] = e1;
            ps[2 * ip]     += e0;
            ps[2 * ip + 1] += e1;
        }
    }

    // ---- block reduction of per-row partial sums ----
    #pragma unroll
    for (int i = 0; i < TI; ++i) {
        #pragma unroll
        for (int o = 16; o > 0; o >>= 1)
            ps[i] += __shfl_xor_sync(0xFFFFFFFFu, ps[i], o);
        if (lane == 0) red[warp][i] = ps[i];
    }
    __syncthreads();
    if (tid < TI) {
        float s = 0.f;
        #pragma unroll
        for (int w = 0; w < 8; ++w) s += red[w][tid];
        g_psum[(size_t)(b * N_ + i0 + tid) * 2 + jh] = s;
    }
}

// ---------------------------------------------------------------------------
// Kernel 3: normalize. 4096 blocks (one row each) x 256 threads (one float4).
// out stays L2-resident between kernels.
// ---------------------------------------------------------------------------
__global__ __launch_bounds__(256) void scale_kernel(float* __restrict__ out)
{
    const int row = blockIdx.x;
    const float s = g_psum[row * 2] + g_psum[row * 2 + 1];
    const float inv = __fdividef(1.f, s);
    float4* o = reinterpret_cast<float4*>(out + (size_t)row * N_);
    float4 v = o[threadIdx.x];
    v.x *= inv; v.y *= inv; v.z *= inv; v.w *= inv;
    o[threadIdx.x] = v;
}

extern "C" void kernel_launch(void* const* d_in, const int* in_sizes, int n_in,
                              void* d_out, int out_size)
{
    const float* x  = (const float*)d_in[0];
    const float* W1 = (const float*)d_in[1];
    const float* W2 = (const float*)d_in[2];
    const float* w3 = (const float*)d_in[3];
    float* out = (float*)d_out;

    proj_kernel<<<M_ / 4, 256>>>(x, W1, W2);

    dim3 grid(N_ / TI, 2, B_);
    att_kernel<<<grid, 256>>>(w3, out);

    scale_kernel<<<M_, 256>>>(out);
}